// round 11
// baseline (speedup 1.0000x reference)
#include <cuda_runtime.h>
#include <cuda_bf16.h>
#include <mma.h>
#include <math.h>
#include <stdint.h>

using namespace nvcuda;

#define Bn 8
#define Tn 2048
#define Dn 1024
#define Hn 4096
#define BT (Bn*Tn)

// ---------------------------------------------------------------------------
// scratch (device globals)
// ---------------------------------------------------------------------------
__device__ float g_q[BT*Dn];
__device__ float g_k[BT*Dn];
__device__ float g_v[BT*Dn];
__device__ float g_num[BT*Dn];
__device__ float g_den[BT*Dn];
__device__ float g_x1[BT*Dn];

__device__ __nv_bfloat16 g_hh[BT*Dn],  g_hl[BT*Dn];          // LN out split (A)
__device__ __nv_bfloat16 g_ewh[Tn*Tn], g_ewl[Tn*Tn];         // exp(pos_bias) split (A)
__device__ __nv_bfloat16 g_ekTh[BT*Dn],  g_ekTl[BT*Dn];      // exp(k)^T per batch (B)
__device__ __nv_bfloat16 g_ekvTh[BT*Dn], g_ekvTl[BT*Dn];     // (exp(k)*v)^T per batch (B)
__device__ __nv_bfloat16 g_wqh[Dn*Dn], g_wql[Dn*Dn];
__device__ __nv_bfloat16 g_wkh[Dn*Dn], g_wkl[Dn*Dn];
__device__ __nv_bfloat16 g_wvh[Dn*Dn], g_wvl[Dn*Dn];
__device__ __nv_bfloat16 g_w1h[Dn*Hn], g_w1l[Dn*Hn];
__device__ __nv_bfloat16 g_w2h[Dn*Hn], g_w2l[Dn*Hn];
__device__ __nv_bfloat16 g_midh[(size_t)BT*Hn], g_midl[(size_t)BT*Hn];

__device__ __forceinline__ void split2(float v, __nv_bfloat16& h, __nv_bfloat16& l) {
    h = __float2bfloat16(v);
    l = __float2bfloat16(v - __bfloat162float(h));
}

// ---------------------------------------------------------------------------
// LayerNorm fused with bf16 split output
// ---------------------------------------------------------------------------
__global__ __launch_bounds__(256) void ln_split_kernel(
    const float* __restrict__ x, const float* __restrict__ gamma,
    const float* __restrict__ beta,
    __nv_bfloat16* __restrict__ oh, __nv_bfloat16* __restrict__ ol)
{
    __shared__ float red[8];
    const int row = blockIdx.x;
    const int tid = threadIdx.x;
    const float4 v = reinterpret_cast<const float4*>(x)[(size_t)row*(Dn/4) + tid];

    float s = v.x + v.y + v.z + v.w;
    #pragma unroll
    for (int o = 16; o > 0; o >>= 1) s += __shfl_xor_sync(0xffffffffu, s, o);
    if ((tid & 31) == 0) red[tid >> 5] = s;
    __syncthreads();
    if (tid == 0) { float t = 0.f; for (int i = 0; i < 8; i++) t += red[i]; red[0] = t; }
    __syncthreads();
    const float mu = red[0] * (1.0f / Dn);

    const float dx = v.x - mu, dy = v.y - mu, dz = v.z - mu, dw = v.w - mu;
    float ss = dx*dx + dy*dy + dz*dz + dw*dw;
    #pragma unroll
    for (int o = 16; o > 0; o >>= 1) ss += __shfl_xor_sync(0xffffffffu, ss, o);
    __syncthreads();
    if ((tid & 31) == 0) red[tid >> 5] = ss;
    __syncthreads();
    if (tid == 0) { float t = 0.f; for (int i = 0; i < 8; i++) t += red[i]; red[0] = t; }
    __syncthreads();
    const float rstd = rsqrtf(red[0] * (1.0f / Dn) + 1e-5f);

    const float4 g4 = reinterpret_cast<const float4*>(gamma)[tid];
    const float4 b4 = reinterpret_cast<const float4*>(beta)[tid];
    float o0 = dx * rstd * g4.x + b4.x;
    float o1 = dy * rstd * g4.y + b4.y;
    float o2 = dz * rstd * g4.z + b4.z;
    float o3 = dw * rstd * g4.w + b4.w;

    __nv_bfloat16 h0,l0,h1,l1,h2,l2,h3,l3;
    split2(o0,h0,l0); split2(o1,h1,l1); split2(o2,h2,l2); split2(o3,h3,l3);
    size_t p = (size_t)row*(Dn/2) + tid*2;
    __nv_bfloat162 a; a.x=h0; a.y=h1;
    __nv_bfloat162 b; b.x=h2; b.y=h3;
    reinterpret_cast<__nv_bfloat162*>(oh)[p]   = a;
    reinterpret_cast<__nv_bfloat162*>(oh)[p+1] = b;
    a.x=l0; a.y=l1; b.x=l2; b.y=l3;
    reinterpret_cast<__nv_bfloat162*>(ol)[p]   = a;
    reinterpret_cast<__nv_bfloat162*>(ol)[p+1] = b;
}

// ---------------------------------------------------------------------------
// convert fp32 -> bf16 hi/lo (optional exp), row-major
// ---------------------------------------------------------------------------
__global__ __launch_bounds__(256) void convert_split_kernel(
    const float* __restrict__ in, __nv_bfloat16* __restrict__ oh,
    __nv_bfloat16* __restrict__ ol, int n4, int doExp)
{
    int i = blockIdx.x * blockDim.x + threadIdx.x;
    if (i >= n4) return;
    float4 v = reinterpret_cast<const float4*>(in)[i];
    if (doExp) { v.x=expf(v.x); v.y=expf(v.y); v.z=expf(v.z); v.w=expf(v.w); }
    __nv_bfloat16 h0,l0,h1,l1,h2,l2,h3,l3;
    split2(v.x,h0,l0); split2(v.y,h1,l1); split2(v.z,h2,l2); split2(v.w,h3,l3);
    __nv_bfloat162 a,b;
    a.x=h0; a.y=h1; b.x=h2; b.y=h3;
    reinterpret_cast<__nv_bfloat162*>(oh)[2*i]   = a;
    reinterpret_cast<__nv_bfloat162*>(oh)[2*i+1] = b;
    a.x=l0; a.y=l1; b.x=l2; b.y=l3;
    reinterpret_cast<__nv_bfloat162*>(ol)[2*i]   = a;
    reinterpret_cast<__nv_bfloat162*>(ol)[2*i+1] = b;
}

// ---------------------------------------------------------------------------
// transpose fp32 [R,C] -> bf16 hi/lo [C,R]; mode 0: plain, 1: exp(a), 2: exp(a)*b
// ---------------------------------------------------------------------------
__global__ __launch_bounds__(256) void transpose_split_kernel(
    const float* __restrict__ in0, const float* __restrict__ in1,
    __nv_bfloat16* __restrict__ oh, __nv_bfloat16* __restrict__ ol,
    int R, int C, long long sIn, long long sOut, int mode)
{
    __shared__ float t[32][33];
    const int z = blockIdx.z;
    in0 += (size_t)z * sIn;
    if (in1) in1 += (size_t)z * sIn;
    oh += (size_t)z * sOut;
    ol += (size_t)z * sOut;

    const int c0 = blockIdx.x * 32;
    const int r0 = blockIdx.y * 32;
    const int tx = threadIdx.x, ty = threadIdx.y;

    #pragma unroll
    for (int j = 0; j < 4; j++) {
        int r = r0 + ty + 8*j;
        float v = in0[(size_t)r * C + c0 + tx];
        if (mode == 1) v = expf(v);
        else if (mode == 2) v = expf(v) * in1[(size_t)r * C + c0 + tx];
        t[ty + 8*j][tx] = v;
    }
    __syncthreads();
    #pragma unroll
    for (int j = 0; j < 4; j++) {
        int oc = ty + 8*j;
        float v = t[tx][oc];
        __nv_bfloat16 h, l;
        split2(v, h, l);
        size_t idx = (size_t)(c0 + oc) * R + r0 + tx;
        oh[idx] = h;
        ol[idx] = l;
    }
}

// ---------------------------------------------------------------------------
// WMMA bf16-split GEMM: C[M,N] = (Ah+Al)[M,K] * ((Bh+Bl)[N,K])^T, fp32 accum.
// 3-MMA scheme: Ah*Bh + Ah*Bl + Al*Bh.
// CTA tile 128x128, BK=32, 8 warps (2x4), warp tile 64x32.
// Double-buffered smem, register prefetch. Epilogue through smem with
// bias/resid/relu and optional bf16-split output.
// ---------------------------------------------------------------------------
#define GBM 128
#define GBN 128
#define GBK 32
#define KPAD 40                       // bf16 elems per row (80B, conflict-free)
#define ARR_B (128*KPAD*2)            // 10240 bytes per operand array
#define STAGE_B (4*ARR_B)             // 40960 bytes (Ah,Al,Bh,Bl)
#define SMEM_G (2*STAGE_B)            // 81920
#define EPILD 132                     // fp32 epilogue stride

__global__ __launch_bounds__(256, 1) void gemm_mma(
    const __nv_bfloat16* __restrict__ Ah, const __nv_bfloat16* __restrict__ Al,
    const __nv_bfloat16* __restrict__ Bh, const __nv_bfloat16* __restrict__ Bl,
    const float* __restrict__ bias, const float* __restrict__ resid,
    float* __restrict__ C, __nv_bfloat16* __restrict__ Ch, __nv_bfloat16* __restrict__ Cl,
    int M, int N, int K, long long sB, long long sC, int relu)
{
    extern __shared__ char smem[];
    const int tid = threadIdx.x;
    const int wid = tid >> 5;
    const int wr = wid >> 2;          // 0..1 : M (64 rows each)
    const int wc = wid & 3;           // 0..3 : N (32 cols each)

    const int z = blockIdx.z;
    Bh += (size_t)z * sB;
    Bl += (size_t)z * sB;
    const size_t cOff = (size_t)z * sC;

    const int rowBase = blockIdx.y * GBM;
    const int colBase = blockIdx.x * GBN;

    wmma::fragment<wmma::accumulator, 16, 16, 16, float> acc[4][2];
    #pragma unroll
    for (int mi = 0; mi < 4; mi++)
        #pragma unroll
        for (int ni = 0; ni < 2; ni++)
            wmma::fill_fragment(acc[mi][ni], 0.0f);

    const int nK = K / GBK;
    uint4 pAh[2], pAl[2], pBh[2], pBl[2];

    // ---- prefetch / store helpers (2 x 16B chunks per operand per thread) ----
    #define LDG_ITER(i) do {                                                   \
        _Pragma("unroll")                                                      \
        for (int j = 0; j < 2; j++) {                                          \
            const int id = tid * 2 + j;                                        \
            const int r = id >> 2, c = id & 3;                                 \
            const size_t ga = (size_t)(rowBase + r) * K + (size_t)(i) * GBK + c * 8; \
            const size_t gb = (size_t)(colBase + r) * K + (size_t)(i) * GBK + c * 8; \
            pAh[j] = *reinterpret_cast<const uint4*>(Ah + ga);                 \
            pAl[j] = *reinterpret_cast<const uint4*>(Al + ga);                 \
            pBh[j] = *reinterpret_cast<const uint4*>(Bh + gb);                 \
            pBl[j] = *reinterpret_cast<const uint4*>(Bl + gb);                 \
        }                                                                      \
    } while (0)

    #define STS_ITER(s) do {                                                   \
        char* st = smem + (s) * STAGE_B;                                       \
        _Pragma("unroll")                                                      \
        for (int j = 0; j < 2; j++) {                                          \
            const int id = tid * 2 + j;                                        \
            const int r = id >> 2, c = id & 3;                                 \
            const int off = r * (KPAD * 2) + c * 16;                           \
            *reinterpret_cast<uint4*>(st + off)             = pAh[j];          \
            *reinterpret_cast<uint4*>(st + ARR_B + off)     = pAl[j];          \
            *reinterpret_cast<uint4*>(st + 2*ARR_B + off)   = pBh[j];          \
            *reinterpret_cast<uint4*>(st + 3*ARR_B + off)   = pBl[j];          \
        }                                                                      \
    } while (0)

    LDG_ITER(0);
    STS_ITER(0);
    __syncthreads();

    for (int i = 0; i < nK; i++) {
        if (i + 1 < nK) LDG_ITER(i + 1);

        const int s = i & 1;
        const __nv_bfloat16* As_h = reinterpret_cast<const __nv_bfloat16*>(smem + s * STAGE_B);
        const __nv_bfloat16* As_l = reinterpret_cast<const __nv_bfloat16*>(smem + s * STAGE_B + ARR_B);
        const __nv_bfloat16* Bs_h = reinterpret_cast<const __nv_bfloat16*>(smem + s * STAGE_B + 2*ARR_B);
        const __nv_bfloat16* Bs_l = reinterpret_cast<const __nv_bfloat16*>(smem + s * STAGE_B + 3*ARR_B);

        #pragma unroll
        for (int kk = 0; kk < 2; kk++) {
            wmma::fragment<wmma::matrix_b, 16, 16, 16, __nv_bfloat16, wmma::col_major> bh[2], bl[2];
            #pragma unroll
            for (int ni = 0; ni < 2; ni++) {
                wmma::load_matrix_sync(bh[ni], Bs_h + (wc*32 + ni*16) * KPAD + kk*16, KPAD);
                wmma::load_matrix_sync(bl[ni], Bs_l + (wc*32 + ni*16) * KPAD + kk*16, KPAD);
            }
            #pragma unroll
            for (int mi = 0; mi < 4; mi++) {
                wmma::fragment<wmma::matrix_a, 16, 16, 16, __nv_bfloat16, wmma::row_major> ah, al;
                wmma::load_matrix_sync(ah, As_h + (wr*64 + mi*16) * KPAD + kk*16, KPAD);
                wmma::load_matrix_sync(al, As_l + (wr*64 + mi*16) * KPAD + kk*16, KPAD);
                #pragma unroll
                for (int ni = 0; ni < 2; ni++) {
                    wmma::mma_sync(acc[mi][ni], ah, bh[ni], acc[mi][ni]);
                    wmma::mma_sync(acc[mi][ni], ah, bl[ni], acc[mi][ni]);
                    wmma::mma_sync(acc[mi][ni], al, bh[ni], acc[mi][ni]);
                }
            }
        }

        if (i + 1 < nK) STS_ITER((i + 1) & 1);
        __syncthreads();
    }

    // ---- epilogue: stage through smem ----
    float* epi = reinterpret_cast<float*>(smem);
    #pragma unroll
    for (int mi = 0; mi < 4; mi++)
        #pragma unroll
        for (int ni = 0; ni < 2; ni++)
            wmma::store_matrix_sync(epi + (wr*64 + mi*16) * EPILD + (wc*32 + ni*16),
                                    acc[mi][ni], EPILD, wmma::mem_row_major);
    __syncthreads();

    const int colQ = (tid & 31) * 4;
    #pragma unroll
    for (int jj = 0; jj < 16; jj++) {
        const int row = (tid >> 5) * 16 + jj;
        float4 o = *reinterpret_cast<const float4*>(epi + row * EPILD + colQ);
        const int gr = rowBase + row;
        const int gc = colBase + colQ;
        if (bias) {
            const float4 bb = *reinterpret_cast<const float4*>(bias + gc);
            o.x += bb.x; o.y += bb.y; o.z += bb.z; o.w += bb.w;
        }
        if (resid) {
            const float4 rr = *reinterpret_cast<const float4*>(resid + cOff + (size_t)gr * N + gc);
            o.x += rr.x; o.y += rr.y; o.z += rr.z; o.w += rr.w;
        }
        if (relu) {
            o.x = fmaxf(o.x, 0.f); o.y = fmaxf(o.y, 0.f);
            o.z = fmaxf(o.z, 0.f); o.w = fmaxf(o.w, 0.f);
        }
        if (C) *reinterpret_cast<float4*>(C + cOff + (size_t)gr * N + gc) = o;
        if (Ch) {
            __nv_bfloat16 h0,l0,h1,l1,h2,l2,h3,l3;
            split2(o.x,h0,l0); split2(o.y,h1,l1);
            split2(o.z,h2,l2); split2(o.w,h3,l3);
            __nv_bfloat162 a,b;
            a.x=h0; a.y=h1; b.x=h2; b.y=h3;
            *reinterpret_cast<__nv_bfloat162*>(Ch + cOff + (size_t)gr * N + gc)     = a;
            *reinterpret_cast<__nv_bfloat162*>(Ch + cOff + (size_t)gr * N + gc + 2) = b;
            a.x=l0; a.y=l1; b.x=l2; b.y=l3;
            *reinterpret_cast<__nv_bfloat162*>(Cl + cOff + (size_t)gr * N + gc)     = a;
            *reinterpret_cast<__nv_bfloat162*>(Cl + cOff + (size_t)gr * N + gc + 2) = b;
        }
    }
    #undef LDG_ITER
    #undef STS_ITER
}

// ---------------------------------------------------------------------------
// x1 = sigmoid(q) * num / den + x
// ---------------------------------------------------------------------------
__global__ __launch_bounds__(256) void combine_kernel(
    const float* __restrict__ q, const float* __restrict__ num,
    const float* __restrict__ den, const float* __restrict__ x,
    float* __restrict__ out, int n4)
{
    int i = blockIdx.x * blockDim.x + threadIdx.x;
    if (i >= n4) return;
    float4 qv = reinterpret_cast<const float4*>(q)[i];
    float4 nv = reinterpret_cast<const float4*>(num)[i];
    float4 dv = reinterpret_cast<const float4*>(den)[i];
    float4 xv = reinterpret_cast<const float4*>(x)[i];
    float4 o;
    o.x = (1.0f / (1.0f + expf(-qv.x))) * (nv.x / dv.x) + xv.x;
    o.y = (1.0f / (1.0f + expf(-qv.y))) * (nv.y / dv.y) + xv.y;
    o.z = (1.0f / (1.0f + expf(-qv.z))) * (nv.z / dv.z) + xv.z;
    o.w = (1.0f / (1.0f + expf(-qv.w))) * (nv.w / dv.w) + xv.w;
    reinterpret_cast<float4*>(out)[i] = o;
}

// ---------------------------------------------------------------------------
// launch
// ---------------------------------------------------------------------------
extern "C" void kernel_launch(void* const* d_in, const int* in_sizes, int n_in,
                              void* d_out, int out_size)
{
    const float* x        = (const float*)d_in[0];
    const float* Wq       = (const float*)d_in[1];
    const float* bq       = (const float*)d_in[2];
    const float* Wk       = (const float*)d_in[3];
    const float* bk       = (const float*)d_in[4];
    const float* Wv       = (const float*)d_in[5];
    const float* bv       = (const float*)d_in[6];
    const float* pos_bias = (const float*)d_in[7];
    const float* ln1_g    = (const float*)d_in[8];
    const float* ln1_b    = (const float*)d_in[9];
    const float* W1       = (const float*)d_in[10];
    const float* b1       = (const float*)d_in[11];
    const float* W2       = (const float*)d_in[12];
    const float* b2       = (const float*)d_in[13];
    const float* ln2_g    = (const float*)d_in[14];
    const float* ln2_b    = (const float*)d_in[15];
    float* out = (float*)d_out;

    float *q,*k,*v,*num,*den,*x1;
    cudaGetSymbolAddress((void**)&q,   g_q);
    cudaGetSymbolAddress((void**)&k,   g_k);
    cudaGetSymbolAddress((void**)&v,   g_v);
    cudaGetSymbolAddress((void**)&num, g_num);
    cudaGetSymbolAddress((void**)&den, g_den);
    cudaGetSymbolAddress((void**)&x1,  g_x1);

    __nv_bfloat16 *hh,*hl,*ewh,*ewl,*ekTh,*ekTl,*ekvTh,*ekvTl;
    __nv_bfloat16 *wqh,*wql,*wkh,*wkl,*wvh,*wvl,*w1h,*w1l,*w2h,*w2l,*midh,*midl;
    cudaGetSymbolAddress((void**)&hh,   g_hh);   cudaGetSymbolAddress((void**)&hl,   g_hl);
    cudaGetSymbolAddress((void**)&ewh,  g_ewh);  cudaGetSymbolAddress((void**)&ewl,  g_ewl);
    cudaGetSymbolAddress((void**)&ekTh, g_ekTh); cudaGetSymbolAddress((void**)&ekTl, g_ekTl);
    cudaGetSymbolAddress((void**)&ekvTh,g_ekvTh);cudaGetSymbolAddress((void**)&ekvTl,g_ekvTl);
    cudaGetSymbolAddress((void**)&wqh,  g_wqh);  cudaGetSymbolAddress((void**)&wql,  g_wql);
    cudaGetSymbolAddress((void**)&wkh,  g_wkh);  cudaGetSymbolAddress((void**)&wkl,  g_wkl);
    cudaGetSymbolAddress((void**)&wvh,  g_wvh);  cudaGetSymbolAddress((void**)&wvl,  g_wvl);
    cudaGetSymbolAddress((void**)&w1h,  g_w1h);  cudaGetSymbolAddress((void**)&w1l,  g_w1l);
    cudaGetSymbolAddress((void**)&w2h,  g_w2h);  cudaGetSymbolAddress((void**)&w2l,  g_w2l);
    cudaGetSymbolAddress((void**)&midh, g_midh); cudaGetSymbolAddress((void**)&midl, g_midl);

    cudaFuncSetAttribute(gemm_mma, cudaFuncAttributeMaxDynamicSharedMemorySize, SMEM_G);

    const long long sTD = (long long)Tn * Dn;
    dim3 tb(32, 8);

    // weight transposes: [K,N] -> [N,K] bf16 split
    transpose_split_kernel<<<dim3(Dn/32, Dn/32, 1), tb>>>(Wq, nullptr, wqh, wql, Dn, Dn, 0, 0, 0);
    transpose_split_kernel<<<dim3(Dn/32, Dn/32, 1), tb>>>(Wk, nullptr, wkh, wkl, Dn, Dn, 0, 0, 0);
    transpose_split_kernel<<<dim3(Dn/32, Dn/32, 1), tb>>>(Wv, nullptr, wvh, wvl, Dn, Dn, 0, 0, 0);
    transpose_split_kernel<<<dim3(Hn/32, Dn/32, 1), tb>>>(W1, nullptr, w1h, w1l, Dn, Hn, 0, 0, 0);
    transpose_split_kernel<<<dim3(Dn/32, Hn/32, 1), tb>>>(W2, nullptr, w2h, w2l, Hn, Dn, 0, 0, 0);

    // ew = exp(pos_bias) split (A operand, row-major)
    convert_split_kernel<<<(Tn*Tn/4 + 255)/256, 256>>>(pos_bias, ewh, ewl, Tn*Tn/4, 1);

    // h = LN1(x) split
    ln_split_kernel<<<BT, 256>>>(x, ln1_g, ln1_b, hh, hl);

    // q/k/v = h @ W + b
    dim3 gQKV(Dn/GBN, BT/GBM, 1);
    gemm_mma<<<gQKV, 256, SMEM_G>>>(hh, hl, wqh, wql, bq, nullptr, q, nullptr, nullptr, BT, Dn, Dn, 0, 0, 0);
    gemm_mma<<<gQKV, 256, SMEM_G>>>(hh, hl, wkh, wkl, bk, nullptr, k, nullptr, nullptr, BT, Dn, Dn, 0, 0, 0);
    gemm_mma<<<gQKV, 256, SMEM_G>>>(hh, hl, wvh, wvl, bv, nullptr, v, nullptr, nullptr, BT, Dn, Dn, 0, 0, 0);

    // ekT = exp(k)^T, ekvT = (exp(k)*v)^T per batch
    transpose_split_kernel<<<dim3(Dn/32, Tn/32, Bn), tb>>>(k, nullptr, ekTh, ekTl, Tn, Dn, sTD, sTD, 1);
    transpose_split_kernel<<<dim3(Dn/32, Tn/32, Bn), tb>>>(k, v, ekvTh, ekvTl, Tn, Dn, sTD, sTD, 2);

    // num = ew @ ekv, den = ew @ ek (batched over B, ew broadcast)
    dim3 gAttn(Dn/GBN, Tn/GBM, Bn);
    gemm_mma<<<gAttn, 256, SMEM_G>>>(ewh, ewl, ekvTh, ekvTl, nullptr, nullptr, num, nullptr, nullptr, Tn, Dn, Tn, sTD, sTD, 0);
    gemm_mma<<<gAttn, 256, SMEM_G>>>(ewh, ewl, ekTh,  ekTl,  nullptr, nullptr, den, nullptr, nullptr, Tn, Dn, Tn, sTD, sTD, 0);

    // x1 = sigmoid(q)*num/den + x
    combine_kernel<<<(BT*Dn/4 + 255)/256, 256>>>(q, num, den, x, x1, BT*Dn/4);

    // h = LN2(x1) split
    ln_split_kernel<<<BT, 256>>>(x1, ln2_g, ln2_b, hh, hl);

    // mid = relu(h @ W1 + b1) -> bf16 split directly
    dim3 gM1(Hn/GBN, BT/GBM, 1);
    gemm_mma<<<gM1, 256, SMEM_G>>>(hh, hl, w1h, w1l, b1, nullptr, nullptr, midh, midl, BT, Hn, Dn, 0, 0, 1);

    // out = mid @ W2 + b2 + x1
    dim3 gM2(Dn/GBN, BT/GBM, 1);
    gemm_mma<<<gM2, 256, SMEM_G>>>(midh, midl, w2h, w2l, b2, x1, out, nullptr, nullptr, BT, Dn, Hn, 0, 0, 0);
}

// round 12
// speedup vs baseline: 1.0008x; 1.0008x over previous
#include <cuda_runtime.h>
#include <cuda_bf16.h>
#include <mma.h>
#include <math.h>
#include <stdint.h>

using namespace nvcuda;

#define Bn 8
#define Tn 2048
#define Dn 1024
#define Hn 4096
#define BT (Bn*Tn)

// ---------------------------------------------------------------------------
// scratch (device globals)
// ---------------------------------------------------------------------------
__device__ float g_q[BT*Dn];
__device__ float g_k[BT*Dn];
__device__ float g_v[BT*Dn];
__device__ float g_num[BT*Dn];
__device__ float g_den[BT*Dn];
__device__ float g_x1[BT*Dn];

__device__ __nv_bfloat16 g_hh[BT*Dn],  g_hl[BT*Dn];          // LN out split (A)
__device__ __nv_bfloat16 g_ewh[Tn*Tn], g_ewl[Tn*Tn];         // exp(pos_bias) split (A)
__device__ __nv_bfloat16 g_ekTh[BT*Dn],  g_ekTl[BT*Dn];      // exp(k)^T per batch (B)
__device__ __nv_bfloat16 g_ekvTh[BT*Dn], g_ekvTl[BT*Dn];     // (exp(k)*v)^T per batch (B)
__device__ __nv_bfloat16 g_wqh[Dn*Dn], g_wql[Dn*Dn];
__device__ __nv_bfloat16 g_wkh[Dn*Dn], g_wkl[Dn*Dn];
__device__ __nv_bfloat16 g_wvh[Dn*Dn], g_wvl[Dn*Dn];
__device__ __nv_bfloat16 g_w1h[Dn*Hn], g_w1l[Dn*Hn];
__device__ __nv_bfloat16 g_w2h[Dn*Hn], g_w2l[Dn*Hn];
__device__ __nv_bfloat16 g_midh[(size_t)BT*Hn], g_midl[(size_t)BT*Hn];

__device__ __forceinline__ void split2(float v, __nv_bfloat16& h, __nv_bfloat16& l) {
    h = __float2bfloat16(v);
    l = __float2bfloat16(v - __bfloat162float(h));
}

// ---------------------------------------------------------------------------
// LayerNorm fused with bf16 split output
// ---------------------------------------------------------------------------
__global__ __launch_bounds__(256) void ln_split_kernel(
    const float* __restrict__ x, const float* __restrict__ gamma,
    const float* __restrict__ beta,
    __nv_bfloat16* __restrict__ oh, __nv_bfloat16* __restrict__ ol)
{
    __shared__ float red[8];
    const int row = blockIdx.x;
    const int tid = threadIdx.x;
    const float4 v = reinterpret_cast<const float4*>(x)[(size_t)row*(Dn/4) + tid];

    float s = v.x + v.y + v.z + v.w;
    #pragma unroll
    for (int o = 16; o > 0; o >>= 1) s += __shfl_xor_sync(0xffffffffu, s, o);
    if ((tid & 31) == 0) red[tid >> 5] = s;
    __syncthreads();
    if (tid == 0) { float t = 0.f; for (int i = 0; i < 8; i++) t += red[i]; red[0] = t; }
    __syncthreads();
    const float mu = red[0] * (1.0f / Dn);

    const float dx = v.x - mu, dy = v.y - mu, dz = v.z - mu, dw = v.w - mu;
    float ss = dx*dx + dy*dy + dz*dz + dw*dw;
    #pragma unroll
    for (int o = 16; o > 0; o >>= 1) ss += __shfl_xor_sync(0xffffffffu, ss, o);
    __syncthreads();
    if ((tid & 31) == 0) red[tid >> 5] = ss;
    __syncthreads();
    if (tid == 0) { float t = 0.f; for (int i = 0; i < 8; i++) t += red[i]; red[0] = t; }
    __syncthreads();
    const float rstd = rsqrtf(red[0] * (1.0f / Dn) + 1e-5f);

    const float4 g4 = reinterpret_cast<const float4*>(gamma)[tid];
    const float4 b4 = reinterpret_cast<const float4*>(beta)[tid];
    float o0 = dx * rstd * g4.x + b4.x;
    float o1 = dy * rstd * g4.y + b4.y;
    float o2 = dz * rstd * g4.z + b4.z;
    float o3 = dw * rstd * g4.w + b4.w;

    __nv_bfloat16 h0,l0,h1,l1,h2,l2,h3,l3;
    split2(o0,h0,l0); split2(o1,h1,l1); split2(o2,h2,l2); split2(o3,h3,l3);
    size_t p = (size_t)row*(Dn/2) + tid*2;
    __nv_bfloat162 a; a.x=h0; a.y=h1;
    __nv_bfloat162 b; b.x=h2; b.y=h3;
    reinterpret_cast<__nv_bfloat162*>(oh)[p]   = a;
    reinterpret_cast<__nv_bfloat162*>(oh)[p+1] = b;
    a.x=l0; a.y=l1; b.x=l2; b.y=l3;
    reinterpret_cast<__nv_bfloat162*>(ol)[p]   = a;
    reinterpret_cast<__nv_bfloat162*>(ol)[p+1] = b;
}

// ---------------------------------------------------------------------------
// convert fp32 -> bf16 hi/lo (optional exp), row-major
// ---------------------------------------------------------------------------
__global__ __launch_bounds__(256) void convert_split_kernel(
    const float* __restrict__ in, __nv_bfloat16* __restrict__ oh,
    __nv_bfloat16* __restrict__ ol, int n4, int doExp)
{
    int i = blockIdx.x * blockDim.x + threadIdx.x;
    if (i >= n4) return;
    float4 v = reinterpret_cast<const float4*>(in)[i];
    if (doExp) { v.x=expf(v.x); v.y=expf(v.y); v.z=expf(v.z); v.w=expf(v.w); }
    __nv_bfloat16 h0,l0,h1,l1,h2,l2,h3,l3;
    split2(v.x,h0,l0); split2(v.y,h1,l1); split2(v.z,h2,l2); split2(v.w,h3,l3);
    __nv_bfloat162 a,b;
    a.x=h0; a.y=h1; b.x=h2; b.y=h3;
    reinterpret_cast<__nv_bfloat162*>(oh)[2*i]   = a;
    reinterpret_cast<__nv_bfloat162*>(oh)[2*i+1] = b;
    a.x=l0; a.y=l1; b.x=l2; b.y=l3;
    reinterpret_cast<__nv_bfloat162*>(ol)[2*i]   = a;
    reinterpret_cast<__nv_bfloat162*>(ol)[2*i+1] = b;
}

// ---------------------------------------------------------------------------
// transpose fp32 [R,C] -> bf16 hi/lo [C,R]; mode 0: plain, 1: exp(a), 2: exp(a)*b
// ---------------------------------------------------------------------------
__global__ __launch_bounds__(256) void transpose_split_kernel(
    const float* __restrict__ in0, const float* __restrict__ in1,
    __nv_bfloat16* __restrict__ oh, __nv_bfloat16* __restrict__ ol,
    int R, int C, long long sIn, long long sOut, int mode)
{
    __shared__ float t[32][33];
    const int z = blockIdx.z;
    in0 += (size_t)z * sIn;
    if (in1) in1 += (size_t)z * sIn;
    oh += (size_t)z * sOut;
    ol += (size_t)z * sOut;

    const int c0 = blockIdx.x * 32;
    const int r0 = blockIdx.y * 32;
    const int tx = threadIdx.x, ty = threadIdx.y;

    #pragma unroll
    for (int j = 0; j < 4; j++) {
        int r = r0 + ty + 8*j;
        float v = in0[(size_t)r * C + c0 + tx];
        if (mode == 1) v = expf(v);
        else if (mode == 2) v = expf(v) * in1[(size_t)r * C + c0 + tx];
        t[ty + 8*j][tx] = v;
    }
    __syncthreads();
    #pragma unroll
    for (int j = 0; j < 4; j++) {
        int oc = ty + 8*j;
        float v = t[tx][oc];
        __nv_bfloat16 h, l;
        split2(v, h, l);
        size_t idx = (size_t)(c0 + oc) * R + r0 + tx;
        oh[idx] = h;
        ol[idx] = l;
    }
}

// ---------------------------------------------------------------------------
// WMMA bf16-split GEMM: C[M,N] = (Ah+Al)[M,K] * ((Bh+Bl)[N,K])^T, fp32 accum.
// 3-MMA scheme: Ah*Bh + Ah*Bl + Al*Bh.
// CTA tile 128x128, BK=32, 8 warps (2x4), warp tile 64x32.
// Double-buffered smem, register prefetch. Epilogue through smem with
// bias/resid/relu and optional bf16-split output.
// ---------------------------------------------------------------------------
#define GBM 128
#define GBN 128
#define GBK 32
#define KPAD 40                       // bf16 elems per row (80B, conflict-free)
#define ARR_B (128*KPAD*2)            // 10240 bytes per operand array
#define STAGE_B (4*ARR_B)             // 40960 bytes (Ah,Al,Bh,Bl)
#define SMEM_G (2*STAGE_B)            // 81920
#define EPILD 132                     // fp32 epilogue stride

__global__ __launch_bounds__(256, 1) void gemm_mma(
    const __nv_bfloat16* __restrict__ Ah, const __nv_bfloat16* __restrict__ Al,
    const __nv_bfloat16* __restrict__ Bh, const __nv_bfloat16* __restrict__ Bl,
    const float* __restrict__ bias, const float* __restrict__ resid,
    float* __restrict__ C, __nv_bfloat16* __restrict__ Ch, __nv_bfloat16* __restrict__ Cl,
    int M, int N, int K, long long sB, long long sC, int relu)
{
    extern __shared__ char smem[];
    const int tid = threadIdx.x;
    const int wid = tid >> 5;
    const int wr = wid >> 2;          // 0..1 : M (64 rows each)
    const int wc = wid & 3;           // 0..3 : N (32 cols each)

    const int z = blockIdx.z;
    Bh += (size_t)z * sB;
    Bl += (size_t)z * sB;
    const size_t cOff = (size_t)z * sC;

    const int rowBase = blockIdx.y * GBM;
    const int colBase = blockIdx.x * GBN;

    wmma::fragment<wmma::accumulator, 16, 16, 16, float> acc[4][2];
    #pragma unroll
    for (int mi = 0; mi < 4; mi++)
        #pragma unroll
        for (int ni = 0; ni < 2; ni++)
            wmma::fill_fragment(acc[mi][ni], 0.0f);

    const int nK = K / GBK;
    uint4 pAh[2], pAl[2], pBh[2], pBl[2];

    // ---- prefetch / store helpers (2 x 16B chunks per operand per thread) ----
    #define LDG_ITER(i) do {                                                   \
        _Pragma("unroll")                                                      \
        for (int j = 0; j < 2; j++) {                                          \
            const int id = tid * 2 + j;                                        \
            const int r = id >> 2, c = id & 3;                                 \
            const size_t ga = (size_t)(rowBase + r) * K + (size_t)(i) * GBK + c * 8; \
            const size_t gb = (size_t)(colBase + r) * K + (size_t)(i) * GBK + c * 8; \
            pAh[j] = *reinterpret_cast<const uint4*>(Ah + ga);                 \
            pAl[j] = *reinterpret_cast<const uint4*>(Al + ga);                 \
            pBh[j] = *reinterpret_cast<const uint4*>(Bh + gb);                 \
            pBl[j] = *reinterpret_cast<const uint4*>(Bl + gb);                 \
        }                                                                      \
    } while (0)

    #define STS_ITER(s) do {                                                   \
        char* st = smem + (s) * STAGE_B;                                       \
        _Pragma("unroll")                                                      \
        for (int j = 0; j < 2; j++) {                                          \
            const int id = tid * 2 + j;                                        \
            const int r = id >> 2, c = id & 3;                                 \
            const int off = r * (KPAD * 2) + c * 16;                           \
            *reinterpret_cast<uint4*>(st + off)             = pAh[j];          \
            *reinterpret_cast<uint4*>(st + ARR_B + off)     = pAl[j];          \
            *reinterpret_cast<uint4*>(st + 2*ARR_B + off)   = pBh[j];          \
            *reinterpret_cast<uint4*>(st + 3*ARR_B + off)   = pBl[j];          \
        }                                                                      \
    } while (0)

    LDG_ITER(0);
    STS_ITER(0);
    __syncthreads();

    for (int i = 0; i < nK; i++) {
        if (i + 1 < nK) LDG_ITER(i + 1);

        const int s = i & 1;
        const __nv_bfloat16* As_h = reinterpret_cast<const __nv_bfloat16*>(smem + s * STAGE_B);
        const __nv_bfloat16* As_l = reinterpret_cast<const __nv_bfloat16*>(smem + s * STAGE_B + ARR_B);
        const __nv_bfloat16* Bs_h = reinterpret_cast<const __nv_bfloat16*>(smem + s * STAGE_B + 2*ARR_B);
        const __nv_bfloat16* Bs_l = reinterpret_cast<const __nv_bfloat16*>(smem + s * STAGE_B + 3*ARR_B);

        #pragma unroll
        for (int kk = 0; kk < 2; kk++) {
            wmma::fragment<wmma::matrix_b, 16, 16, 16, __nv_bfloat16, wmma::col_major> bh[2], bl[2];
            #pragma unroll
            for (int ni = 0; ni < 2; ni++) {
                wmma::load_matrix_sync(bh[ni], Bs_h + (wc*32 + ni*16) * KPAD + kk*16, KPAD);
                wmma::load_matrix_sync(bl[ni], Bs_l + (wc*32 + ni*16) * KPAD + kk*16, KPAD);
            }
            #pragma unroll
            for (int mi = 0; mi < 4; mi++) {
                wmma::fragment<wmma::matrix_a, 16, 16, 16, __nv_bfloat16, wmma::row_major> ah, al;
                wmma::load_matrix_sync(ah, As_h + (wr*64 + mi*16) * KPAD + kk*16, KPAD);
                wmma::load_matrix_sync(al, As_l + (wr*64 + mi*16) * KPAD + kk*16, KPAD);
                #pragma unroll
                for (int ni = 0; ni < 2; ni++) {
                    wmma::mma_sync(acc[mi][ni], ah, bh[ni], acc[mi][ni]);
                    wmma::mma_sync(acc[mi][ni], ah, bl[ni], acc[mi][ni]);
                    wmma::mma_sync(acc[mi][ni], al, bh[ni], acc[mi][ni]);
                }
            }
        }

        if (i + 1 < nK) STS_ITER((i + 1) & 1);
        __syncthreads();
    }

    // ---- epilogue: stage through smem ----
    float* epi = reinterpret_cast<float*>(smem);
    #pragma unroll
    for (int mi = 0; mi < 4; mi++)
        #pragma unroll
        for (int ni = 0; ni < 2; ni++)
            wmma::store_matrix_sync(epi + (wr*64 + mi*16) * EPILD + (wc*32 + ni*16),
                                    acc[mi][ni], EPILD, wmma::mem_row_major);
    __syncthreads();

    const int colQ = (tid & 31) * 4;
    #pragma unroll
    for (int jj = 0; jj < 16; jj++) {
        const int row = (tid >> 5) * 16 + jj;
        float4 o = *reinterpret_cast<const float4*>(epi + row * EPILD + colQ);
        const int gr = rowBase + row;
        const int gc = colBase + colQ;
        if (bias) {
            const float4 bb = *reinterpret_cast<const float4*>(bias + gc);
            o.x += bb.x; o.y += bb.y; o.z += bb.z; o.w += bb.w;
        }
        if (resid) {
            const float4 rr = *reinterpret_cast<const float4*>(resid + cOff + (size_t)gr * N + gc);
            o.x += rr.x; o.y += rr.y; o.z += rr.z; o.w += rr.w;
        }
        if (relu) {
            o.x = fmaxf(o.x, 0.f); o.y = fmaxf(o.y, 0.f);
            o.z = fmaxf(o.z, 0.f); o.w = fmaxf(o.w, 0.f);
        }
        if (C) *reinterpret_cast<float4*>(C + cOff + (size_t)gr * N + gc) = o;
        if (Ch) {
            __nv_bfloat16 h0,l0,h1,l1,h2,l2,h3,l3;
            split2(o.x,h0,l0); split2(o.y,h1,l1);
            split2(o.z,h2,l2); split2(o.w,h3,l3);
            __nv_bfloat162 a,b;
            a.x=h0; a.y=h1; b.x=h2; b.y=h3;
            *reinterpret_cast<__nv_bfloat162*>(Ch + cOff + (size_t)gr * N + gc)     = a;
            *reinterpret_cast<__nv_bfloat162*>(Ch + cOff + (size_t)gr * N + gc + 2) = b;
            a.x=l0; a.y=l1; b.x=l2; b.y=l3;
            *reinterpret_cast<__nv_bfloat162*>(Cl + cOff + (size_t)gr * N + gc)     = a;
            *reinterpret_cast<__nv_bfloat162*>(Cl + cOff + (size_t)gr * N + gc + 2) = b;
        }
    }
    #undef LDG_ITER
    #undef STS_ITER
}

// ---------------------------------------------------------------------------
// x1 = sigmoid(q) * num / den + x
// ---------------------------------------------------------------------------
__global__ __launch_bounds__(256) void combine_kernel(
    const float* __restrict__ q, const float* __restrict__ num,
    const float* __restrict__ den, const float* __restrict__ x,
    float* __restrict__ out, int n4)
{
    int i = blockIdx.x * blockDim.x + threadIdx.x;
    if (i >= n4) return;
    float4 qv = reinterpret_cast<const float4*>(q)[i];
    float4 nv = reinterpret_cast<const float4*>(num)[i];
    float4 dv = reinterpret_cast<const float4*>(den)[i];
    float4 xv = reinterpret_cast<const float4*>(x)[i];
    float4 o;
    o.x = (1.0f / (1.0f + expf(-qv.x))) * (nv.x / dv.x) + xv.x;
    o.y = (1.0f / (1.0f + expf(-qv.y))) * (nv.y / dv.y) + xv.y;
    o.z = (1.0f / (1.0f + expf(-qv.z))) * (nv.z / dv.z) + xv.z;
    o.w = (1.0f / (1.0f + expf(-qv.w))) * (nv.w / dv.w) + xv.w;
    reinterpret_cast<float4*>(out)[i] = o;
}

// ---------------------------------------------------------------------------
// launch
// ---------------------------------------------------------------------------
extern "C" void kernel_launch(void* const* d_in, const int* in_sizes, int n_in,
                              void* d_out, int out_size)
{
    const float* x        = (const float*)d_in[0];
    const float* Wq       = (const float*)d_in[1];
    const float* bq       = (const float*)d_in[2];
    const float* Wk       = (const float*)d_in[3];
    const float* bk       = (const float*)d_in[4];
    const float* Wv       = (const float*)d_in[5];
    const float* bv       = (const float*)d_in[6];
    const float* pos_bias = (const float*)d_in[7];
    const float* ln1_g    = (const float*)d_in[8];
    const float* ln1_b    = (const float*)d_in[9];
    const float* W1       = (const float*)d_in[10];
    const float* b1       = (const float*)d_in[11];
    const float* W2       = (const float*)d_in[12];
    const float* b2       = (const float*)d_in[13];
    const float* ln2_g    = (const float*)d_in[14];
    const float* ln2_b    = (const float*)d_in[15];
    float* out = (float*)d_out;

    float *q,*k,*v,*num,*den,*x1;
    cudaGetSymbolAddress((void**)&q,   g_q);
    cudaGetSymbolAddress((void**)&k,   g_k);
    cudaGetSymbolAddress((void**)&v,   g_v);
    cudaGetSymbolAddress((void**)&num, g_num);
    cudaGetSymbolAddress((void**)&den, g_den);
    cudaGetSymbolAddress((void**)&x1,  g_x1);

    __nv_bfloat16 *hh,*hl,*ewh,*ewl,*ekTh,*ekTl,*ekvTh,*ekvTl;
    __nv_bfloat16 *wqh,*wql,*wkh,*wkl,*wvh,*wvl,*w1h,*w1l,*w2h,*w2l,*midh,*midl;
    cudaGetSymbolAddress((void**)&hh,   g_hh);   cudaGetSymbolAddress((void**)&hl,   g_hl);
    cudaGetSymbolAddress((void**)&ewh,  g_ewh);  cudaGetSymbolAddress((void**)&ewl,  g_ewl);
    cudaGetSymbolAddress((void**)&ekTh, g_ekTh); cudaGetSymbolAddress((void**)&ekTl, g_ekTl);
    cudaGetSymbolAddress((void**)&ekvTh,g_ekvTh);cudaGetSymbolAddress((void**)&ekvTl,g_ekvTl);
    cudaGetSymbolAddress((void**)&wqh,  g_wqh);  cudaGetSymbolAddress((void**)&wql,  g_wql);
    cudaGetSymbolAddress((void**)&wkh,  g_wkh);  cudaGetSymbolAddress((void**)&wkl,  g_wkl);
    cudaGetSymbolAddress((void**)&wvh,  g_wvh);  cudaGetSymbolAddress((void**)&wvl,  g_wvl);
    cudaGetSymbolAddress((void**)&w1h,  g_w1h);  cudaGetSymbolAddress((void**)&w1l,  g_w1l);
    cudaGetSymbolAddress((void**)&w2h,  g_w2h);  cudaGetSymbolAddress((void**)&w2l,  g_w2l);
    cudaGetSymbolAddress((void**)&midh, g_midh); cudaGetSymbolAddress((void**)&midl, g_midl);

    cudaFuncSetAttribute(gemm_mma, cudaFuncAttributeMaxDynamicSharedMemorySize, SMEM_G);

    const long long sTD = (long long)Tn * Dn;
    dim3 tb(32, 8);

    // weight transposes: [K,N] -> [N,K] bf16 split
    transpose_split_kernel<<<dim3(Dn/32, Dn/32, 1), tb>>>(Wq, nullptr, wqh, wql, Dn, Dn, 0, 0, 0);
    transpose_split_kernel<<<dim3(Dn/32, Dn/32, 1), tb>>>(Wk, nullptr, wkh, wkl, Dn, Dn, 0, 0, 0);
    transpose_split_kernel<<<dim3(Dn/32, Dn/32, 1), tb>>>(Wv, nullptr, wvh, wvl, Dn, Dn, 0, 0, 0);
    transpose_split_kernel<<<dim3(Hn/32, Dn/32, 1), tb>>>(W1, nullptr, w1h, w1l, Dn, Hn, 0, 0, 0);
    transpose_split_kernel<<<dim3(Dn/32, Hn/32, 1), tb>>>(W2, nullptr, w2h, w2l, Hn, Dn, 0, 0, 0);

    // ew = exp(pos_bias) split (A operand, row-major)
    convert_split_kernel<<<(Tn*Tn/4 + 255)/256, 256>>>(pos_bias, ewh, ewl, Tn*Tn/4, 1);

    // h = LN1(x) split
    ln_split_kernel<<<BT, 256>>>(x, ln1_g, ln1_b, hh, hl);

    // q/k/v = h @ W + b
    dim3 gQKV(Dn/GBN, BT/GBM, 1);
    gemm_mma<<<gQKV, 256, SMEM_G>>>(hh, hl, wqh, wql, bq, nullptr, q, nullptr, nullptr, BT, Dn, Dn, 0, 0, 0);
    gemm_mma<<<gQKV, 256, SMEM_G>>>(hh, hl, wkh, wkl, bk, nullptr, k, nullptr, nullptr, BT, Dn, Dn, 0, 0, 0);
    gemm_mma<<<gQKV, 256, SMEM_G>>>(hh, hl, wvh, wvl, bv, nullptr, v, nullptr, nullptr, BT, Dn, Dn, 0, 0, 0);

    // ekT = exp(k)^T, ekvT = (exp(k)*v)^T per batch
    transpose_split_kernel<<<dim3(Dn/32, Tn/32, Bn), tb>>>(k, nullptr, ekTh, ekTl, Tn, Dn, sTD, sTD, 1);
    transpose_split_kernel<<<dim3(Dn/32, Tn/32, Bn), tb>>>(k, v, ekvTh, ekvTl, Tn, Dn, sTD, sTD, 2);

    // num = ew @ ekv, den = ew @ ek (batched over B, ew broadcast)
    dim3 gAttn(Dn/GBN, Tn/GBM, Bn);
    gemm_mma<<<gAttn, 256, SMEM_G>>>(ewh, ewl, ekvTh, ekvTl, nullptr, nullptr, num, nullptr, nullptr, Tn, Dn, Tn, sTD, sTD, 0);
    gemm_mma<<<gAttn, 256, SMEM_G>>>(ewh, ewl, ekTh,  ekTl,  nullptr, nullptr, den, nullptr, nullptr, Tn, Dn, Tn, sTD, sTD, 0);

    // x1 = sigmoid(q)*num/den + x
    combine_kernel<<<(BT*Dn/4 + 255)/256, 256>>>(q, num, den, x, x1, BT*Dn/4);

    // h = LN2(x1) split
    ln_split_kernel<<<BT, 256>>>(x1, ln2_g, ln2_b, hh, hl);

    // mid = relu(h @ W1 + b1) -> bf16 split directly
    dim3 gM1(Hn/GBN, BT/GBM, 1);
    gemm_mma<<<gM1, 256, SMEM_G>>>(hh, hl, w1h, w1l, b1, nullptr, nullptr, midh, midl, BT, Hn, Dn, 0, 0, 1);

    // out = mid @ W2 + b2 + x1
    dim3 gM2(Dn/GBN, BT/GBM, 1);
    gemm_mma<<<gM2, 256, SMEM_G>>>(midh, midl, w2h, w2l, b2, x1, out, nullptr, nullptr, BT, Dn, Hn, 0, 0, 0);
}

// round 13
// speedup vs baseline: 1.0032x; 1.0024x over previous
#include <cuda_runtime.h>
#include <cuda_bf16.h>
#include <mma.h>
#include <math.h>
#include <stdint.h>

using namespace nvcuda;

#define Bn 8
#define Tn 2048
#define Dn 1024
#define Hn 4096
#define BT (Bn*Tn)

// ---------------------------------------------------------------------------
// scratch (device globals)
// ---------------------------------------------------------------------------
__device__ float g_q[BT*Dn];
__device__ float g_k[BT*Dn];
__device__ float g_v[BT*Dn];
__device__ float g_num[BT*Dn];
__device__ float g_den[BT*Dn];
__device__ float g_x1[BT*Dn];

__device__ __nv_bfloat16 g_hh[BT*Dn],  g_hl[BT*Dn];          // LN out split (A)
__device__ __nv_bfloat16 g_ewh[Tn*Tn], g_ewl[Tn*Tn];         // exp(pos_bias) split (A)
__device__ __nv_bfloat16 g_ekTh[BT*Dn],  g_ekTl[BT*Dn];      // exp(k)^T per batch (B)
__device__ __nv_bfloat16 g_ekvTh[BT*Dn], g_ekvTl[BT*Dn];     // (exp(k)*v)^T per batch (B)
__device__ __nv_bfloat16 g_wqh[Dn*Dn], g_wql[Dn*Dn];
__device__ __nv_bfloat16 g_wkh[Dn*Dn], g_wkl[Dn*Dn];
__device__ __nv_bfloat16 g_wvh[Dn*Dn], g_wvl[Dn*Dn];
__device__ __nv_bfloat16 g_w1h[Dn*Hn], g_w1l[Dn*Hn];
__device__ __nv_bfloat16 g_w2h[Dn*Hn], g_w2l[Dn*Hn];
__device__ __nv_bfloat16 g_midh[(size_t)BT*Hn], g_midl[(size_t)BT*Hn];

__device__ __forceinline__ void split2(float v, __nv_bfloat16& h, __nv_bfloat16& l) {
    h = __float2bfloat16(v);
    l = __float2bfloat16(v - __bfloat162float(h));
}

// ---------------------------------------------------------------------------
// LayerNorm fused with bf16 split output
// ---------------------------------------------------------------------------
__global__ __launch_bounds__(256) void ln_split_kernel(
    const float* __restrict__ x, const float* __restrict__ gamma,
    const float* __restrict__ beta,
    __nv_bfloat16* __restrict__ oh, __nv_bfloat16* __restrict__ ol)
{
    __shared__ float red[8];
    const int row = blockIdx.x;
    const int tid = threadIdx.x;
    const float4 v = reinterpret_cast<const float4*>(x)[(size_t)row*(Dn/4) + tid];

    float s = v.x + v.y + v.z + v.w;
    #pragma unroll
    for (int o = 16; o > 0; o >>= 1) s += __shfl_xor_sync(0xffffffffu, s, o);
    if ((tid & 31) == 0) red[tid >> 5] = s;
    __syncthreads();
    if (tid == 0) { float t = 0.f; for (int i = 0; i < 8; i++) t += red[i]; red[0] = t; }
    __syncthreads();
    const float mu = red[0] * (1.0f / Dn);

    const float dx = v.x - mu, dy = v.y - mu, dz = v.z - mu, dw = v.w - mu;
    float ss = dx*dx + dy*dy + dz*dz + dw*dw;
    #pragma unroll
    for (int o = 16; o > 0; o >>= 1) ss += __shfl_xor_sync(0xffffffffu, ss, o);
    __syncthreads();
    if ((tid & 31) == 0) red[tid >> 5] = ss;
    __syncthreads();
    if (tid == 0) { float t = 0.f; for (int i = 0; i < 8; i++) t += red[i]; red[0] = t; }
    __syncthreads();
    const float rstd = rsqrtf(red[0] * (1.0f / Dn) + 1e-5f);

    const float4 g4 = reinterpret_cast<const float4*>(gamma)[tid];
    const float4 b4 = reinterpret_cast<const float4*>(beta)[tid];
    float o0 = dx * rstd * g4.x + b4.x;
    float o1 = dy * rstd * g4.y + b4.y;
    float o2 = dz * rstd * g4.z + b4.z;
    float o3 = dw * rstd * g4.w + b4.w;

    __nv_bfloat16 h0,l0,h1,l1,h2,l2,h3,l3;
    split2(o0,h0,l0); split2(o1,h1,l1); split2(o2,h2,l2); split2(o3,h3,l3);
    size_t p = (size_t)row*(Dn/2) + tid*2;
    __nv_bfloat162 a; a.x=h0; a.y=h1;
    __nv_bfloat162 b; b.x=h2; b.y=h3;
    reinterpret_cast<__nv_bfloat162*>(oh)[p]   = a;
    reinterpret_cast<__nv_bfloat162*>(oh)[p+1] = b;
    a.x=l0; a.y=l1; b.x=l2; b.y=l3;
    reinterpret_cast<__nv_bfloat162*>(ol)[p]   = a;
    reinterpret_cast<__nv_bfloat162*>(ol)[p+1] = b;
}

// ---------------------------------------------------------------------------
// convert fp32 -> bf16 hi/lo (optional exp), row-major
// ---------------------------------------------------------------------------
__global__ __launch_bounds__(256) void convert_split_kernel(
    const float* __restrict__ in, __nv_bfloat16* __restrict__ oh,
    __nv_bfloat16* __restrict__ ol, int n4, int doExp)
{
    int i = blockIdx.x * blockDim.x + threadIdx.x;
    if (i >= n4) return;
    float4 v = reinterpret_cast<const float4*>(in)[i];
    if (doExp) { v.x=expf(v.x); v.y=expf(v.y); v.z=expf(v.z); v.w=expf(v.w); }
    __nv_bfloat16 h0,l0,h1,l1,h2,l2,h3,l3;
    split2(v.x,h0,l0); split2(v.y,h1,l1); split2(v.z,h2,l2); split2(v.w,h3,l3);
    __nv_bfloat162 a,b;
    a.x=h0; a.y=h1; b.x=h2; b.y=h3;
    reinterpret_cast<__nv_bfloat162*>(oh)[2*i]   = a;
    reinterpret_cast<__nv_bfloat162*>(oh)[2*i+1] = b;
    a.x=l0; a.y=l1; b.x=l2; b.y=l3;
    reinterpret_cast<__nv_bfloat162*>(ol)[2*i]   = a;
    reinterpret_cast<__nv_bfloat162*>(ol)[2*i+1] = b;
}

// ---------------------------------------------------------------------------
// transpose fp32 [R,C] -> bf16 hi/lo [C,R]; mode 0: plain, 1: exp(a), 2: exp(a)*b
// ---------------------------------------------------------------------------
__global__ __launch_bounds__(256) void transpose_split_kernel(
    const float* __restrict__ in0, const float* __restrict__ in1,
    __nv_bfloat16* __restrict__ oh, __nv_bfloat16* __restrict__ ol,
    int R, int C, long long sIn, long long sOut, int mode)
{
    __shared__ float t[32][33];
    const int z = blockIdx.z;
    in0 += (size_t)z * sIn;
    if (in1) in1 += (size_t)z * sIn;
    oh += (size_t)z * sOut;
    ol += (size_t)z * sOut;

    const int c0 = blockIdx.x * 32;
    const int r0 = blockIdx.y * 32;
    const int tx = threadIdx.x, ty = threadIdx.y;

    #pragma unroll
    for (int j = 0; j < 4; j++) {
        int r = r0 + ty + 8*j;
        float v = in0[(size_t)r * C + c0 + tx];
        if (mode == 1) v = expf(v);
        else if (mode == 2) v = expf(v) * in1[(size_t)r * C + c0 + tx];
        t[ty + 8*j][tx] = v;
    }
    __syncthreads();
    #pragma unroll
    for (int j = 0; j < 4; j++) {
        int oc = ty + 8*j;
        float v = t[tx][oc];
        __nv_bfloat16 h, l;
        split2(v, h, l);
        size_t idx = (size_t)(c0 + oc) * R + r0 + tx;
        oh[idx] = h;
        ol[idx] = l;
    }
}

// ---------------------------------------------------------------------------
// WMMA bf16-split GEMM: C[M,N] = (Ah+Al)[M,K] * ((Bh+Bl)[N,K])^T, fp32 accum.
// 3-MMA scheme: Ah*Bh + Ah*Bl + Al*Bh.
// CTA tile 128x128, BK=32, 8 warps (2x4), warp tile 64x32.
// Double-buffered smem, register prefetch. Epilogue through smem with
// bias/resid/relu and optional bf16-split output.
// ---------------------------------------------------------------------------
#define GBM 128
#define GBN 128
#define GBK 32
#define KPAD 40                       // bf16 elems per row (80B, conflict-free)
#define ARR_B (128*KPAD*2)            // 10240 bytes per operand array
#define STAGE_B (4*ARR_B)             // 40960 bytes (Ah,Al,Bh,Bl)
#define SMEM_G (2*STAGE_B)            // 81920
#define EPILD 132                     // fp32 epilogue stride

__global__ __launch_bounds__(256, 1) void gemm_mma(
    const __nv_bfloat16* __restrict__ Ah, const __nv_bfloat16* __restrict__ Al,
    const __nv_bfloat16* __restrict__ Bh, const __nv_bfloat16* __restrict__ Bl,
    const float* __restrict__ bias, const float* __restrict__ resid,
    float* __restrict__ C, __nv_bfloat16* __restrict__ Ch, __nv_bfloat16* __restrict__ Cl,
    int M, int N, int K, long long sB, long long sC, int relu)
{
    extern __shared__ char smem[];
    const int tid = threadIdx.x;
    const int wid = tid >> 5;
    const int wr = wid >> 2;          // 0..1 : M (64 rows each)
    const int wc = wid & 3;           // 0..3 : N (32 cols each)

    const int z = blockIdx.z;
    Bh += (size_t)z * sB;
    Bl += (size_t)z * sB;
    const size_t cOff = (size_t)z * sC;

    const int rowBase = blockIdx.y * GBM;
    const int colBase = blockIdx.x * GBN;

    wmma::fragment<wmma::accumulator, 16, 16, 16, float> acc[4][2];
    #pragma unroll
    for (int mi = 0; mi < 4; mi++)
        #pragma unroll
        for (int ni = 0; ni < 2; ni++)
            wmma::fill_fragment(acc[mi][ni], 0.0f);

    const int nK = K / GBK;
    uint4 pAh[2], pAl[2], pBh[2], pBl[2];

    // ---- prefetch / store helpers (2 x 16B chunks per operand per thread) ----
    #define LDG_ITER(i) do {                                                   \
        _Pragma("unroll")                                                      \
        for (int j = 0; j < 2; j++) {                                          \
            const int id = tid * 2 + j;                                        \
            const int r = id >> 2, c = id & 3;                                 \
            const size_t ga = (size_t)(rowBase + r) * K + (size_t)(i) * GBK + c * 8; \
            const size_t gb = (size_t)(colBase + r) * K + (size_t)(i) * GBK + c * 8; \
            pAh[j] = *reinterpret_cast<const uint4*>(Ah + ga);                 \
            pAl[j] = *reinterpret_cast<const uint4*>(Al + ga);                 \
            pBh[j] = *reinterpret_cast<const uint4*>(Bh + gb);                 \
            pBl[j] = *reinterpret_cast<const uint4*>(Bl + gb);                 \
        }                                                                      \
    } while (0)

    #define STS_ITER(s) do {                                                   \
        char* st = smem + (s) * STAGE_B;                                       \
        _Pragma("unroll")                                                      \
        for (int j = 0; j < 2; j++) {                                          \
            const int id = tid * 2 + j;                                        \
            const int r = id >> 2, c = id & 3;                                 \
            const int off = r * (KPAD * 2) + c * 16;                           \
            *reinterpret_cast<uint4*>(st + off)             = pAh[j];          \
            *reinterpret_cast<uint4*>(st + ARR_B + off)     = pAl[j];          \
            *reinterpret_cast<uint4*>(st + 2*ARR_B + off)   = pBh[j];          \
            *reinterpret_cast<uint4*>(st + 3*ARR_B + off)   = pBl[j];          \
        }                                                                      \
    } while (0)

    LDG_ITER(0);
    STS_ITER(0);
    __syncthreads();

    for (int i = 0; i < nK; i++) {
        if (i + 1 < nK) LDG_ITER(i + 1);

        const int s = i & 1;
        const __nv_bfloat16* As_h = reinterpret_cast<const __nv_bfloat16*>(smem + s * STAGE_B);
        const __nv_bfloat16* As_l = reinterpret_cast<const __nv_bfloat16*>(smem + s * STAGE_B + ARR_B);
        const __nv_bfloat16* Bs_h = reinterpret_cast<const __nv_bfloat16*>(smem + s * STAGE_B + 2*ARR_B);
        const __nv_bfloat16* Bs_l = reinterpret_cast<const __nv_bfloat16*>(smem + s * STAGE_B + 3*ARR_B);

        #pragma unroll
        for (int kk = 0; kk < 2; kk++) {
            wmma::fragment<wmma::matrix_b, 16, 16, 16, __nv_bfloat16, wmma::col_major> bh[2], bl[2];
            #pragma unroll
            for (int ni = 0; ni < 2; ni++) {
                wmma::load_matrix_sync(bh[ni], Bs_h + (wc*32 + ni*16) * KPAD + kk*16, KPAD);
                wmma::load_matrix_sync(bl[ni], Bs_l + (wc*32 + ni*16) * KPAD + kk*16, KPAD);
            }
            #pragma unroll
            for (int mi = 0; mi < 4; mi++) {
                wmma::fragment<wmma::matrix_a, 16, 16, 16, __nv_bfloat16, wmma::row_major> ah, al;
                wmma::load_matrix_sync(ah, As_h + (wr*64 + mi*16) * KPAD + kk*16, KPAD);
                wmma::load_matrix_sync(al, As_l + (wr*64 + mi*16) * KPAD + kk*16, KPAD);
                #pragma unroll
                for (int ni = 0; ni < 2; ni++) {
                    wmma::mma_sync(acc[mi][ni], ah, bh[ni], acc[mi][ni]);
                    wmma::mma_sync(acc[mi][ni], ah, bl[ni], acc[mi][ni]);
                    wmma::mma_sync(acc[mi][ni], al, bh[ni], acc[mi][ni]);
                }
            }
        }

        if (i + 1 < nK) STS_ITER((i + 1) & 1);
        __syncthreads();
    }

    // ---- epilogue: stage through smem ----
    float* epi = reinterpret_cast<float*>(smem);
    #pragma unroll
    for (int mi = 0; mi < 4; mi++)
        #pragma unroll
        for (int ni = 0; ni < 2; ni++)
            wmma::store_matrix_sync(epi + (wr*64 + mi*16) * EPILD + (wc*32 + ni*16),
                                    acc[mi][ni], EPILD, wmma::mem_row_major);
    __syncthreads();

    const int colQ = (tid & 31) * 4;
    #pragma unroll
    for (int jj = 0; jj < 16; jj++) {
        const int row = (tid >> 5) * 16 + jj;
        float4 o = *reinterpret_cast<const float4*>(epi + row * EPILD + colQ);
        const int gr = rowBase + row;
        const int gc = colBase + colQ;
        if (bias) {
            const float4 bb = *reinterpret_cast<const float4*>(bias + gc);
            o.x += bb.x; o.y += bb.y; o.z += bb.z; o.w += bb.w;
        }
        if (resid) {
            const float4 rr = *reinterpret_cast<const float4*>(resid + cOff + (size_t)gr * N + gc);
            o.x += rr.x; o.y += rr.y; o.z += rr.z; o.w += rr.w;
        }
        if (relu) {
            o.x = fmaxf(o.x, 0.f); o.y = fmaxf(o.y, 0.f);
            o.z = fmaxf(o.z, 0.f); o.w = fmaxf(o.w, 0.f);
        }
        if (C) *reinterpret_cast<float4*>(C + cOff + (size_t)gr * N + gc) = o;
        if (Ch) {
            __nv_bfloat16 h0,l0,h1,l1,h2,l2,h3,l3;
            split2(o.x,h0,l0); split2(o.y,h1,l1);
            split2(o.z,h2,l2); split2(o.w,h3,l3);
            __nv_bfloat162 a,b;
            a.x=h0; a.y=h1; b.x=h2; b.y=h3;
            *reinterpret_cast<__nv_bfloat162*>(Ch + cOff + (size_t)gr * N + gc)     = a;
            *reinterpret_cast<__nv_bfloat162*>(Ch + cOff + (size_t)gr * N + gc + 2) = b;
            a.x=l0; a.y=l1; b.x=l2; b.y=l3;
            *reinterpret_cast<__nv_bfloat162*>(Cl + cOff + (size_t)gr * N + gc)     = a;
            *reinterpret_cast<__nv_bfloat162*>(Cl + cOff + (size_t)gr * N + gc + 2) = b;
        }
    }
    #undef LDG_ITER
    #undef STS_ITER
}

// ---------------------------------------------------------------------------
// x1 = sigmoid(q) * num / den + x
// ---------------------------------------------------------------------------
__global__ __launch_bounds__(256) void combine_kernel(
    const float* __restrict__ q, const float* __restrict__ num,
    const float* __restrict__ den, const float* __restrict__ x,
    float* __restrict__ out, int n4)
{
    int i = blockIdx.x * blockDim.x + threadIdx.x;
    if (i >= n4) return;
    float4 qv = reinterpret_cast<const float4*>(q)[i];
    float4 nv = reinterpret_cast<const float4*>(num)[i];
    float4 dv = reinterpret_cast<const float4*>(den)[i];
    float4 xv = reinterpret_cast<const float4*>(x)[i];
    float4 o;
    o.x = (1.0f / (1.0f + expf(-qv.x))) * (nv.x / dv.x) + xv.x;
    o.y = (1.0f / (1.0f + expf(-qv.y))) * (nv.y / dv.y) + xv.y;
    o.z = (1.0f / (1.0f + expf(-qv.z))) * (nv.z / dv.z) + xv.z;
    o.w = (1.0f / (1.0f + expf(-qv.w))) * (nv.w / dv.w) + xv.w;
    reinterpret_cast<float4*>(out)[i] = o;
}

// ---------------------------------------------------------------------------
// launch
// ---------------------------------------------------------------------------
extern "C" void kernel_launch(void* const* d_in, const int* in_sizes, int n_in,
                              void* d_out, int out_size)
{
    const float* x        = (const float*)d_in[0];
    const float* Wq       = (const float*)d_in[1];
    const float* bq       = (const float*)d_in[2];
    const float* Wk       = (const float*)d_in[3];
    const float* bk       = (const float*)d_in[4];
    const float* Wv       = (const float*)d_in[5];
    const float* bv       = (const float*)d_in[6];
    const float* pos_bias = (const float*)d_in[7];
    const float* ln1_g    = (const float*)d_in[8];
    const float* ln1_b    = (const float*)d_in[9];
    const float* W1       = (const float*)d_in[10];
    const float* b1       = (const float*)d_in[11];
    const float* W2       = (const float*)d_in[12];
    const float* b2       = (const float*)d_in[13];
    const float* ln2_g    = (const float*)d_in[14];
    const float* ln2_b    = (const float*)d_in[15];
    float* out = (float*)d_out;

    float *q,*k,*v,*num,*den,*x1;
    cudaGetSymbolAddress((void**)&q,   g_q);
    cudaGetSymbolAddress((void**)&k,   g_k);
    cudaGetSymbolAddress((void**)&v,   g_v);
    cudaGetSymbolAddress((void**)&num, g_num);
    cudaGetSymbolAddress((void**)&den, g_den);
    cudaGetSymbolAddress((void**)&x1,  g_x1);

    __nv_bfloat16 *hh,*hl,*ewh,*ewl,*ekTh,*ekTl,*ekvTh,*ekvTl;
    __nv_bfloat16 *wqh,*wql,*wkh,*wkl,*wvh,*wvl,*w1h,*w1l,*w2h,*w2l,*midh,*midl;
    cudaGetSymbolAddress((void**)&hh,   g_hh);   cudaGetSymbolAddress((void**)&hl,   g_hl);
    cudaGetSymbolAddress((void**)&ewh,  g_ewh);  cudaGetSymbolAddress((void**)&ewl,  g_ewl);
    cudaGetSymbolAddress((void**)&ekTh, g_ekTh); cudaGetSymbolAddress((void**)&ekTl, g_ekTl);
    cudaGetSymbolAddress((void**)&ekvTh,g_ekvTh);cudaGetSymbolAddress((void**)&ekvTl,g_ekvTl);
    cudaGetSymbolAddress((void**)&wqh,  g_wqh);  cudaGetSymbolAddress((void**)&wql,  g_wql);
    cudaGetSymbolAddress((void**)&wkh,  g_wkh);  cudaGetSymbolAddress((void**)&wkl,  g_wkl);
    cudaGetSymbolAddress((void**)&wvh,  g_wvh);  cudaGetSymbolAddress((void**)&wvl,  g_wvl);
    cudaGetSymbolAddress((void**)&w1h,  g_w1h);  cudaGetSymbolAddress((void**)&w1l,  g_w1l);
    cudaGetSymbolAddress((void**)&w2h,  g_w2h);  cudaGetSymbolAddress((void**)&w2l,  g_w2l);
    cudaGetSymbolAddress((void**)&midh, g_midh); cudaGetSymbolAddress((void**)&midl, g_midl);

    cudaFuncSetAttribute(gemm_mma, cudaFuncAttributeMaxDynamicSharedMemorySize, SMEM_G);

    const long long sTD = (long long)Tn * Dn;
    dim3 tb(32, 8);

    // weight transposes: [K,N] -> [N,K] bf16 split
    transpose_split_kernel<<<dim3(Dn/32, Dn/32, 1), tb>>>(Wq, nullptr, wqh, wql, Dn, Dn, 0, 0, 0);
    transpose_split_kernel<<<dim3(Dn/32, Dn/32, 1), tb>>>(Wk, nullptr, wkh, wkl, Dn, Dn, 0, 0, 0);
    transpose_split_kernel<<<dim3(Dn/32, Dn/32, 1), tb>>>(Wv, nullptr, wvh, wvl, Dn, Dn, 0, 0, 0);
    transpose_split_kernel<<<dim3(Hn/32, Dn/32, 1), tb>>>(W1, nullptr, w1h, w1l, Dn, Hn, 0, 0, 0);
    transpose_split_kernel<<<dim3(Dn/32, Hn/32, 1), tb>>>(W2, nullptr, w2h, w2l, Hn, Dn, 0, 0, 0);

    // ew = exp(pos_bias) split (A operand, row-major)
    convert_split_kernel<<<(Tn*Tn/4 + 255)/256, 256>>>(pos_bias, ewh, ewl, Tn*Tn/4, 1);

    // h = LN1(x) split
    ln_split_kernel<<<BT, 256>>>(x, ln1_g, ln1_b, hh, hl);

    // q/k/v = h @ W + b
    dim3 gQKV(Dn/GBN, BT/GBM, 1);
    gemm_mma<<<gQKV, 256, SMEM_G>>>(hh, hl, wqh, wql, bq, nullptr, q, nullptr, nullptr, BT, Dn, Dn, 0, 0, 0);
    gemm_mma<<<gQKV, 256, SMEM_G>>>(hh, hl, wkh, wkl, bk, nullptr, k, nullptr, nullptr, BT, Dn, Dn, 0, 0, 0);
    gemm_mma<<<gQKV, 256, SMEM_G>>>(hh, hl, wvh, wvl, bv, nullptr, v, nullptr, nullptr, BT, Dn, Dn, 0, 0, 0);

    // ekT = exp(k)^T, ekvT = (exp(k)*v)^T per batch
    transpose_split_kernel<<<dim3(Dn/32, Tn/32, Bn), tb>>>(k, nullptr, ekTh, ekTl, Tn, Dn, sTD, sTD, 1);
    transpose_split_kernel<<<dim3(Dn/32, Tn/32, Bn), tb>>>(k, v, ekvTh, ekvTl, Tn, Dn, sTD, sTD, 2);

    // num = ew @ ekv, den = ew @ ek (batched over B, ew broadcast)
    dim3 gAttn(Dn/GBN, Tn/GBM, Bn);
    gemm_mma<<<gAttn, 256, SMEM_G>>>(ewh, ewl, ekvTh, ekvTl, nullptr, nullptr, num, nullptr, nullptr, Tn, Dn, Tn, sTD, sTD, 0);
    gemm_mma<<<gAttn, 256, SMEM_G>>>(ewh, ewl, ekTh,  ekTl,  nullptr, nullptr, den, nullptr, nullptr, Tn, Dn, Tn, sTD, sTD, 0);

    // x1 = sigmoid(q)*num/den + x
    combine_kernel<<<(BT*Dn/4 + 255)/256, 256>>>(q, num, den, x, x1, BT*Dn/4);

    // h = LN2(x1) split
    ln_split_kernel<<<BT, 256>>>(x1, ln2_g, ln2_b, hh, hl);

    // mid = relu(h @ W1 + b1) -> bf16 split directly
    dim3 gM1(Hn/GBN, BT/GBM, 1);
    gemm_mma<<<gM1, 256, SMEM_G>>>(hh, hl, w1h, w1l, b1, nullptr, nullptr, midh, midl, BT, Hn, Dn, 0, 0, 1);

    // out = mid @ W2 + b2 + x1
    dim3 gM2(Dn/GBN, BT/GBM, 1);
    gemm_mma<<<gM2, 256, SMEM_G>>>(midh, midl, w2h, w2l, b2, x1, out, nullptr, nullptr, BT, Dn, Hn, 0, 0, 0);
}